// round 12
// baseline (speedup 1.0000x reference)
#include <cuda_runtime.h>
#include <cstdint>

// Problem constants
#define NNODES 50000
#define R      6
#define E      32768
#define H      256
#define F      16
#define NH     8
#define HD     32
#define KVDIM  272      // H + F
#define HHALF  128      // H/2

// ---------------- scratch arena (lifetime-aliased) ----------------
constexpr long KV_F = (long)R * E * KVDIM;
constexpr long QE_F = (long)R * E * H;

constexpr long OFF_KV  = 0;
constexpr long OFF_QE  = OFF_KV + KV_F;
constexpr long OFF_K   = OFF_QE + QE_F;
constexpr long OFF_V   = OFF_K + QE_F;
constexpr long ENDA    = OFF_V + QE_F;

// tf32 copies of x/eattr live in the dead KV region (dead before PATHS is written)
constexpr long OFF_XTF = 0;                                 // N*H
constexpr long OFF_ETF = OFF_XTF + (long)NNODES * H;        // R*E*F
static_assert(OFF_ETF + (long)R * E * F <= KV_F, "xtf/etf overflow");

// aliases into [0, ENDA): qe/k/v (and xtf/etf) dead by the time these are written
constexpr long OFF_PATHS = 0;
constexpr long OFF_STK   = OFF_PATHS + (long)3 * NNODES * H;
constexpr long OFF_T     = OFF_STK + (long)3 * NNODES * H;
constexpr long OFF_CAT   = OFF_T + (long)3 * NNODES * HHALF;
constexpr long OFF_COMB  = OFF_CAT + (long)NNODES * 2 * H;
static_assert(OFF_COMB + (long)NNODES * H <= ENDA, "alias overflow");

constexpr long OFF_AGG    = ENDA;
constexpr long OFF_REL    = OFF_AGG + (long)R * NNODES * H;
constexpr long OFF_EX     = OFF_REL + (long)R * NNODES * H;
constexpr long OFF_DEN    = OFF_EX + (long)R * E * NH;
constexpr long OFF_H1     = OFF_DEN + (long)R * NNODES * NH;
constexpr long OFF_IW     = OFF_H1 + (long)NNODES * H;

// transposed+tf32 weights tail  (dst[b][n][k] = cvt(src[b][k][n]))
constexpr long OFF_WT  = OFF_IW + (long)NNODES * R;
constexpr long TWQ   = OFF_WT;                  // 6*256*256
constexpr long TWK   = TWQ  + 6L * 256 * 256;   // 6*272*256  (as [256 n][272 k])
constexpr long TWV   = TWK  + 6L * 272 * 256;
constexpr long TWM   = TWV  + 6L * 272 * 256;   // 6*256*256
constexpr long TWIR1 = TWM  + 6L * 256 * 256;   // [256 n][1536 k]
constexpr long TWMP  = TWIR1 + 1536L * 256;     // 3*256*256
constexpr long TWA1  = TWMP + 3L * 256 * 256;   // [128 n][256 k]
constexpr long TWC   = TWA1 + 256L * 128;       // [256 n][512 k]
constexpr long ARENA_F = TWC + 512L * 256;

__device__ __align__(16) float g_arena[ARENA_F];

// ---------------- helpers ----------------
template<int EPI>
__device__ __forceinline__ float act(float v) {
    if (EPI == 1) return 0.5f * v * (1.f + erff(v * 0.70710678118654752f)); // exact gelu
    if (EPI == 2) return tanhf(v);
    return v;
}

__device__ __forceinline__ uint32_t f2tf32(float f) {
    uint32_t u;
    asm("cvt.rna.tf32.f32 %0, %1;" : "=r"(u) : "f"(f));
    return u;
}

__device__ __forceinline__ void mma8(float* d, const uint32_t* a, const uint32_t* b) {
    asm volatile("mma.sync.aligned.m16n8k8.row.col.f32.tf32.tf32.f32 "
        "{%0,%1,%2,%3}, {%4,%5,%6,%7}, {%8,%9}, {%0,%1,%2,%3};"
        : "+f"(d[0]), "+f"(d[1]), "+f"(d[2]), "+f"(d[3])
        : "r"(a[0]), "r"(a[1]), "r"(a[2]), "r"(a[3]), "r"(b[0]), "r"(b[1]));
}

#define LDSM4(r0, r1, r2, r3, addr) \
    asm volatile("ldmatrix.sync.aligned.m8n8.x4.shared.b16 {%0,%1,%2,%3}, [%4];" \
        : "=r"(r0), "=r"(r1), "=r"(r2), "=r"(r3) : "r"(addr))

__device__ __forceinline__ uint32_t smem_u32(const void* p) {
    return (uint32_t)__cvta_generic_to_shared(p);
}

__device__ __forceinline__ void cp16(uint32_t dst, const void* src, int sz) {
    asm volatile("cp.async.cg.shared.global [%0], [%1], 16, %2;"
                 :: "r"(dst), "l"(src), "r"(sz));
}

__device__ __forceinline__ float blockReduceSum256(float v, float* red) {
    #pragma unroll
    for (int o = 16; o; o >>= 1) v += __shfl_xor_sync(0xffffffffu, v, o);
    int lane = threadIdx.x & 31, w = threadIdx.x >> 5;
    if (lane == 0) red[w] = v;
    __syncthreads();
    float s = (threadIdx.x < 8) ? red[threadIdx.x] : 0.f;
    if (w == 0) {
        #pragma unroll
        for (int o = 4; o; o >>= 1) s += __shfl_xor_sync(0xffffffffu, s, o);
        if (lane == 0) red[0] = s;
    }
    __syncthreads();
    s = red[0];
    __syncthreads();
    return s;
}

// ---------------- prepass: tf32 rounding / weight transpose ----------------
__global__ void cvt_kernel(const float* __restrict__ src, long dstOff, long n) {
    long i = (long)blockIdx.x * 256 + threadIdx.x;
    if (i < n) g_arena[dstOff + i] = __uint_as_float(f2tf32(src[i]));
}

// dst linear: b*N*K + n*K + k  =  cvt(src[b*K*N + k*N + n])
__global__ void trans_kernel(const float* __restrict__ src, long dstOff, int K, int N, int nb) {
    long i = (long)blockIdx.x * 256 + threadIdx.x;
    long tot = (long)K * N * nb;
    if (i >= tot) return;
    int k = (int)(i % K);
    long t2 = i / K;
    int n = (int)(t2 % N);
    int b = (int)(t2 / N);
    g_arena[dstOff + i] = __uint_as_float(f2tf32(src[((long)b * K + k) * N + n]));
}

// ---------------- batched TF32 GEMM: 3-stage cp.async + ldmatrix + XOR swizzle
// Stage layout (A and B identical): [128 rows][16 floats], XOR chunk-swizzle:
//   logical 4-float chunk c of row r stored at chunk c ^ ((r>>1)&3).
// 3 stages x (8KB A + 8KB B) = 49,152 B static (== 48KB cap).
// All operands loaded via ldmatrix.x4.b16 (4 tf32 = one 16B "b16 row").
// ATF32=true: A source already tf32 (no cvt); false: cvt.rna the LDSM regs.
// A source by MODE: 0 arena linear | 1 xtf gather | 2 xtf/etf concat | 3 R-concat
#define NSTAGE 3
constexpr int STG_F = 128 * 16;            // 2048 floats per stage
constexpr uint32_t STG_B = STG_F * 4;      // 8192 bytes

template<int EPI, int MODE, bool ATF32>
__global__ __launch_bounds__(256)
void tgemm(long aOff, long bOff, const float* __restrict__ bias,
           long cOff, int M, int Nc, int K,
           long sA, long sB, long sBias, long sC,
           const int* __restrict__ aidx, long sIdx)
{
    __shared__ __align__(16) float Asm[NSTAGE * STG_F];
    __shared__ __align__(16) float Bsm[NSTAGE * STG_F];

    int bz = blockIdx.z;
    const float* biasp = bias + bz * sBias;
    float* C = g_arena + cOff + bz * sC;

    int t = threadIdx.x;
    int m0 = blockIdx.y * 128, n0 = blockIdx.x * 128;

    int arow = t >> 1, acolg = (t & 1) * 8;    // per-thread: row, 8-float col group

    int gr = m0 + arow;
    bool avalid = gr < M;
    int asz = avalid ? 16 : 0;                 // 0 => cp.async zero-fill
    int grc = avalid ? gr : 0;

    // A source base
    const float* abase = nullptr;
    const float* a2base = nullptr;
    if (MODE == 0) abase = g_arena + aOff + bz * sA + (long)grc * K + acolg;
    if (MODE == 1) abase = g_arena + OFF_XTF + (long)aidx[bz * sIdx + grc] * 256 + acolg;
    if (MODE == 2) {
        abase  = g_arena + OFF_XTF + (long)aidx[bz * sIdx + grc] * 256;
        a2base = g_arena + OFF_ETF + ((long)bz * E + grc) * 16;
    }
    if (MODE == 3) a2base = g_arena + aOff + (long)grc * 256;

    // B source: transposed weights [Nc][K]
    const float* bbase = g_arena + bOff + bz * sB + (long)(n0 + arow) * K + acolg;

    // swizzled cp.async destinations (chunk = 4 floats = 16B)
    int wsw = (arow >> 1) & 3;                       // write swizzle for this row
    int c0 = (acolg >> 2), c1 = c0 + 1;              // logical chunks {0,1} or {2,3}
    uint32_t rowB = (uint32_t)(arow * 64);           // row byte offset
    uint32_t aD1 = smem_u32(Asm) + rowB + (uint32_t)((c0 ^ wsw) << 4);
    uint32_t aD2 = smem_u32(Asm) + rowB + (uint32_t)((c1 ^ wsw) << 4);
    uint32_t bD1 = smem_u32(Bsm) + rowB + (uint32_t)((c0 ^ wsw) << 4);
    uint32_t bD2 = smem_u32(Bsm) + rowB + (uint32_t)((c1 ^ wsw) << 4);

    int lane = t & 31, w = t >> 5;
    int gid = lane >> 2, tig = lane & 3;
    int wm0 = (w & 1) * 64, wn0 = (w >> 1) * 32;

    // ldmatrix per-thread row/chunk (b16 m8n8 trick: 1 matrix row = 4 tf32)
    uint32_t aRow = (uint32_t)((lane & 7) + ((lane >> 3) & 1) * 8);
    uint32_t aChk = (uint32_t)(lane >> 4);           // 0/1
    uint32_t aRB[4]; int aSW[4];
    #pragma unroll
    for (int mf = 0; mf < 4; mf++) {
        uint32_t row = (uint32_t)(wm0 + mf * 16) + aRow;
        aRB[mf] = smem_u32(Asm) + row * 64;
        aSW[mf] = (int)((row >> 1) & 3);
    }
    uint32_t bRow = (uint32_t)((lane & 7) + (lane >> 4) * 8);
    uint32_t bChk = (uint32_t)((lane >> 3) & 1);     // 0/1
    uint32_t bRB[2]; int bSW[2];
    #pragma unroll
    for (int p = 0; p < 2; p++) {
        uint32_t row = (uint32_t)(wn0 + p * 16) + bRow;
        bRB[p] = smem_u32(Bsm) + row * 64;
        bSW[p] = (int)((row >> 1) & 3);
    }

    float d[4][4][4];
    #pragma unroll
    for (int mf = 0; mf < 4; mf++)
        #pragma unroll
        for (int nf = 0; nf < 4; nf++)
            #pragma unroll
            for (int i = 0; i < 4; i++) d[mf][nf][i] = 0.f;

    int T = K >> 4;

    auto issue = [&](int kt, int s) {
        const float* ap;
        if (MODE == 0 || MODE == 1) {
            ap = abase + (long)kt * 16;
        } else if (MODE == 2) {
            int kcol = kt * 16 + acolg;
            ap = (kcol < 256) ? (abase + kcol) : (a2base + (kcol - 256));
        } else { // MODE 3
            int kcol = kt * 16 + acolg;
            int b = kcol >> 8;
            ap = a2base + (long)b * sA + (kcol & 255);
        }
        uint32_t so = (uint32_t)s * STG_B;
        cp16(aD1 + so, ap, asz);
        cp16(aD2 + so, ap + 4, asz);
        const float* bp = bbase + (long)kt * 16;
        cp16(bD1 + so, bp, 16);
        cp16(bD2 + so, bp + 4, 16);
    };

    // prologue: fill 2 stages
    #pragma unroll
    for (int p = 0; p < NSTAGE - 1; p++) {
        if (p < T) issue(p, p);
        asm volatile("cp.async.commit_group;");
    }

    int s = 0;
    for (int kt = 0; kt < T; kt++) {
        asm volatile("cp.async.wait_group 1;" ::: "memory");
        __syncthreads();                       // all warps past prev reads of recycled stage
        int ktn = kt + NSTAGE - 1;
        int sn = s + NSTAGE - 1; if (sn >= NSTAGE) sn -= NSTAGE;
        if (ktn < T) issue(ktn, sn);
        asm volatile("cp.async.commit_group;");

        uint32_t sOff = (uint32_t)s * STG_B;
        #pragma unroll
        for (int ks = 0; ks < 16; ks += 8) {
            int clA = (int)aChk + ((ks >> 3) << 1);   // logical chunk for A ldsm
            int clB = (int)bChk + ((ks >> 3) << 1);
            uint32_t af[4][4], bf[4][2];
            #pragma unroll
            for (int mf = 0; mf < 4; mf++) {
                LDSM4(af[mf][0], af[mf][1], af[mf][2], af[mf][3],
                      aRB[mf] + sOff + (uint32_t)(((clA ^ aSW[mf])) << 4));
                if (!ATF32) {
                    #pragma unroll
                    for (int i = 0; i < 4; i++)
                        af[mf][i] = f2tf32(__uint_as_float(af[mf][i]));
                }
            }
            LDSM4(bf[0][0], bf[0][1], bf[1][0], bf[1][1],
                  bRB[0] + sOff + (uint32_t)(((clB ^ bSW[0])) << 4));
            LDSM4(bf[2][0], bf[2][1], bf[3][0], bf[3][1],
                  bRB[1] + sOff + (uint32_t)(((clB ^ bSW[1])) << 4));
            #pragma unroll
            for (int mf = 0; mf < 4; mf++)
                #pragma unroll
                for (int nf = 0; nf < 4; nf++)
                    mma8(d[mf][nf], af[mf], bf[nf]);
        }
        if (++s == NSTAGE) s = 0;
    }

    // epilogue
    #pragma unroll
    for (int mf = 0; mf < 4; mf++) {
        int r0 = m0 + wm0 + mf * 16 + gid;
        int r1 = r0 + 8;
        #pragma unroll
        for (int nf = 0; nf < 4; nf++) {
            int c0e = n0 + wn0 + nf * 8 + tig * 2;
            float bb0 = biasp[c0e], bb1 = biasp[c0e + 1];
            if (r0 < M) {
                float* cp = C + (long)r0 * Nc + c0e;
                cp[0] = act<EPI>(d[mf][nf][0] + bb0);
                cp[1] = act<EPI>(d[mf][nf][1] + bb1);
            }
            if (r1 < M) {
                float* cp = C + (long)r1 * Nc + c0e;
                cp[0] = act<EPI>(d[mf][nf][2] + bb0);
                cp[1] = act<EPI>(d[mf][nf][3] + bb1);
            }
        }
    }
}

// ---------------- elementwise / scatter kernels ----------------
__global__ void zero_kernel() {
    long i = (long)blockIdx.x * 256 + threadIdx.x;
    float4 z = make_float4(0.f, 0.f, 0.f, 0.f);
    if (i < (long)R * NNODES * H / 4)  ((float4*)(g_arena + OFF_AGG))[i] = z;
    if (i < (long)R * NNODES * NH / 4) ((float4*)(g_arena + OFF_DEN))[i] = z;
}

// ex = exp(score); denom[dst] += ex   (no max-sub: scores are bounded ~|4|)
__global__ void scores_kernel(const int* __restrict__ ei, const float* __restrict__ prior) {
    int t = blockIdx.x * 256 + threadIdx.x;
    if (t >= R * E * NH) return;
    int nh = t & 7;
    int e  = (t >> 3) & (E - 1);
    int r  = t >> 18;
    long base = ((long)r * E + e) * H + nh * HD;
    const float4* q4 = (const float4*)(g_arena + OFF_QE + base);
    const float4* k4 = (const float4*)(g_arena + OFF_K + base);
    float s = 0.f;
    #pragma unroll
    for (int i = 0; i < 8; i++) {
        float4 a = q4[i], b = k4[i];
        s += a.x*b.x + a.y*b.y + a.z*b.z + a.w*b.w;
    }
    s *= 0.17677669529663687f;      // 1/sqrt(32)
    s *= prior[r * NH + nh];
    float ex = expf(s);
    g_arena[OFF_EX + ((long)r * E + e) * NH + nh] = ex;
    int dst = ei[((long)r * 2 + 1) * E + e];
    atomicAdd(&g_arena[OFF_DEN + ((long)r * NNODES + dst) * NH + nh], ex);
}

// agg[dst] += w * v  (8 dims per thread, vectorized f32 reductions)
__global__ void scatter_kernel(const int* __restrict__ ei) {
    int t = blockIdx.x * 256 + threadIdx.x;
    if (t >= R * E * NH * 4) return;
    int c  = t & 3;
    int nh = (t >> 2) & 7;
    int e  = (t >> 5) & (E - 1);
    int r  = t >> 20;
    int dst = ei[((long)r * 2 + 1) * E + e];
    float ex = g_arena[OFF_EX + ((long)r * E + e) * NH + nh];
    float dn = g_arena[OFF_DEN + ((long)r * NNODES + dst) * NH + nh];
    float w = ex / (dn + 1e-16f);
    long vb = ((long)r * E + e) * H + nh * HD + c * 8;
    float4 v0 = *(const float4*)(g_arena + OFF_V + vb);
    float4 v1 = *(const float4*)(g_arena + OFF_V + vb + 4);
    float* ag = g_arena + OFF_AGG + ((long)r * NNODES + dst) * H + nh * HD + c * 8;
    asm volatile("red.global.add.v4.f32 [%0], {%1,%2,%3,%4};"
                 :: "l"(ag), "f"(w*v0.x), "f"(w*v0.y), "f"(w*v0.z), "f"(w*v0.w) : "memory");
    asm volatile("red.global.add.v4.f32 [%0], {%1,%2,%3,%4};"
                 :: "l"(ag+4), "f"(w*v1.x), "f"(w*v1.y), "f"(w*v1.z), "f"(w*v1.w) : "memory");
}

// inter_w[n,:] = softmax(h1[n,:] @ W_ir2 + b_ir2)   (one warp per node)
__global__ void irw_kernel(const float* __restrict__ W_ir2, const float* __restrict__ b_ir2) {
    int gt = blockIdx.x * 256 + threadIdx.x;
    int warp = gt >> 5, lane = gt & 31;
    if (warp >= NNODES) return;
    const float* hr = g_arena + OFF_H1 + (long)warp * H;
    float acc[R];
    #pragma unroll
    for (int r = 0; r < R; r++) acc[r] = 0.f;
    for (int k = lane; k < H; k += 32) {
        float hv = hr[k];
        #pragma unroll
        for (int r = 0; r < R; r++) acc[r] += hv * W_ir2[k * R + r];
    }
    #pragma unroll
    for (int r = 0; r < R; r++)
        #pragma unroll
        for (int o = 16; o; o >>= 1) acc[r] += __shfl_xor_sync(0xffffffffu, acc[r], o);
    if (lane == 0) {
        float l[R], mx = -1e30f;
        #pragma unroll
        for (int r = 0; r < R; r++) { l[r] = acc[r] + b_ir2[r]; mx = fmaxf(mx, l[r]); }
        float s = 0.f;
        #pragma unroll
        for (int r = 0; r < R; r++) { l[r] = expf(l[r] - mx); s += l[r]; }
        #pragma unroll
        for (int r = 0; r < R; r++) g_arena[OFF_IW + (long)warp * R + r] = l[r] / s;
    }
}

// inter_agg -> cat[:, 0:256]; meta-paths -> paths[3,N,H]
__global__ void fuse1_kernel() {
    int t = blockIdx.x * 256 + threadIdx.x;
    if (t >= NNODES * 64) return;
    int h4 = t & 63;
    long n = t >> 6;
    float w[R];
    #pragma unroll
    for (int r = 0; r < R; r++) w[r] = g_arena[OFF_IW + n * R + r];
    float4 rv[R];
    #pragma unroll
    for (int r = 0; r < R; r++)
        rv[r] = ((const float4*)(g_arena + OFF_REL))[((long)r * NNODES + n) * 64 + h4];
    float4 ia;
    ia.x = ia.y = ia.z = ia.w = 0.f;
    #pragma unroll
    for (int r = 0; r < R; r++) {
        ia.x += w[r] * rv[r].x; ia.y += w[r] * rv[r].y;
        ia.z += w[r] * rv[r].z; ia.w += w[r] * rv[r].w;
    }
    ((float4*)(g_arena + OFF_CAT))[n * 128 + h4] = ia;
    float4 p0, p1, p2;
    p0.x = rv[2].x + rv[3].x; p0.y = rv[2].y + rv[3].y; p0.z = rv[2].z + rv[3].z; p0.w = rv[2].w + rv[3].w;
    p1.x = rv[4].x + rv[0].x; p1.y = rv[4].y + rv[0].y; p1.z = rv[4].z + rv[0].z; p1.w = rv[4].w + rv[0].w;
    p2.x = rv[1].x + rv[5].x; p2.y = rv[1].y + rv[5].y; p2.z = rv[1].z + rv[5].z; p2.w = rv[1].w + rv[5].w;
    float4* pp = (float4*)(g_arena + OFF_PATHS);
    pp[((long)0 * NNODES + n) * 64 + h4] = p0;
    pp[((long)1 * NNODES + n) * 64 + h4] = p1;
    pp[((long)2 * NNODES + n) * 64 + h4] = p2;
}

// path-attention + weighted sum + LN -> cat[:, 256:512]   (block per node)
__global__ void meta_kernel(const float* __restrict__ Wa2,
                            const float* __restrict__ g_meta, const float* __restrict__ b_meta) {
    __shared__ float red[8];
    __shared__ float sw[3];
    long n = blockIdx.x;
    int t = threadIdx.x;
    float p0 = 0.f, p1 = 0.f, p2 = 0.f;
    if (t < HHALF) {
        float w2 = Wa2[t];
        const float* tb = g_arena + OFF_T;
        p0 = tb[((long)0 * NNODES + n) * HHALF + t] * w2;
        p1 = tb[((long)1 * NNODES + n) * HHALF + t] * w2;
        p2 = tb[((long)2 * NNODES + n) * HHALF + t] * w2;
    }
    float l0 = blockReduceSum256(p0, red);
    float l1 = blockReduceSum256(p1, red);
    float l2 = blockReduceSum256(p2, red);
    if (t == 0) {
        float mx = fmaxf(l0, fmaxf(l1, l2));
        float e0 = expf(l0 - mx), e1 = expf(l1 - mx), e2 = expf(l2 - mx);
        float s = e0 + e1 + e2;
        sw[0] = e0 / s; sw[1] = e1 / s; sw[2] = e2 / s;
    }
    __syncthreads();
    const float* sb = g_arena + OFF_STK;
    float mp = sw[0] * sb[((long)0 * NNODES + n) * H + t]
             + sw[1] * sb[((long)1 * NNODES + n) * H + t]
             + sw[2] * sb[((long)2 * NNODES + n) * H + t];
    float s1 = blockReduceSum256(mp, red);
    float s2 = blockReduceSum256(mp * mp, red);
    float mu = s1 * (1.f / H);
    float var = s2 * (1.f / H) - mu * mu;
    g_arena[OFF_CAT + n * 512 + 256 + t] =
        (mp - mu) * rsqrtf(var + 1e-5f) * g_meta[t] + b_meta[t];
}

// out = LN(x + combined)
__global__ void final_kernel(const float* __restrict__ x,
                             const float* __restrict__ g, const float* __restrict__ b,
                             float* __restrict__ out) {
    __shared__ float red[8];
    long n = blockIdx.x;
    int t = threadIdx.x;
    float v = x[n * H + t] + g_arena[OFF_COMB + n * H + t];
    float s1 = blockReduceSum256(v, red);
    float s2 = blockReduceSum256(v * v, red);
    float mu = s1 * (1.f / H);
    float var = s2 * (1.f / H) - mu * mu;
    out[n * H + t] = (v - mu) * rsqrtf(var + 1e-5f) * g[t] + b[t];
}

// ---------------- launcher ----------------
extern "C" void kernel_launch(void* const* d_in, const int* in_sizes, int n_in,
                              void* d_out, int out_size) {
    const float* x      = (const float*)d_in[0];
    const int*   ei     = (const int*)  d_in[1];
    const float* eattr  = (const float*)d_in[2];
    const float* Wq     = (const float*)d_in[3];
    const float* bq     = (const float*)d_in[4];
    const float* Wk     = (const float*)d_in[5];
    const float* bk     = (const float*)d_in[6];
    const float* Wv     = (const float*)d_in[7];
    const float* bv     = (const float*)d_in[8];
    const float* prior  = (const float*)d_in[9];
    const float* Wm     = (const float*)d_in[10];
    const float* bm     = (const float*)d_in[11];
    const float* W_ir1  = (const float*)d_in[12];
    const float* b_ir1  = (const float*)d_in[13];
    const float* W_ir2  = (const float*)d_in[14];
    const float* b_ir2  = (const float*)d_in[15];
    const float* Wmp    = (const float*)d_in[16];
    const float* bmp    = (const float*)d_in[17];
    const float* Wa1    = (const float*)d_in[18];
    const float* ba1    = (const float*)d_in[19];
    const float* Wa2    = (const float*)d_in[20];
    const float* g_meta = (const float*)d_in[21];
    const float* b_meta = (const float*)d_in[22];
    const float* Wc     = (const float*)d_in[23];
    const float* bc     = (const float*)d_in[24];
    const float* g_out  = (const float*)d_in[25];
    const float* b_out  = (const float*)d_in[26];
    float* out = (float*)d_out;

    const int GM_N = (NNODES + 127) / 128;   // 391
    const int GM_E = E / 128;                // 256

    // 0: prepass — tf32 copies of x/eattr, transposed tf32 weights
    cvt_kernel<<<(int)(((long)NNODES * H + 255) / 256), 256>>>(x, OFF_XTF, (long)NNODES * H);
    cvt_kernel<<<(int)(((long)R * E * F + 255) / 256), 256>>>(eattr, OFF_ETF, (long)R * E * F);
    trans_kernel<<<(6 * 256 * 256 + 255) / 256, 256>>>(Wq, TWQ, 256, 256, 6);
    trans_kernel<<<(6 * 272 * 256 + 255) / 256, 256>>>(Wk, TWK, 272, 256, 6);
    trans_kernel<<<(6 * 272 * 256 + 255) / 256, 256>>>(Wv, TWV, 272, 256, 6);
    trans_kernel<<<(6 * 256 * 256 + 255) / 256, 256>>>(Wm, TWM, 256, 256, 6);
    trans_kernel<<<(1536 * 256 + 255) / 256, 256>>>(W_ir1, TWIR1, 1536, 256, 1);
    trans_kernel<<<(3 * 256 * 256 + 255) / 256, 256>>>(Wmp, TWMP, 256, 256, 3);
    trans_kernel<<<(256 * 128 + 255) / 256, 256>>>(Wa1, TWA1, 256, 128, 1);
    trans_kernel<<<(512 * 256 + 255) / 256, 256>>>(Wc, TWC, 512, 256, 1);
    // 1: zero accumulators (agg, denom) — float4 stores
    zero_kernel<<<(int)((((long)R * NNODES * H / 4) + 255) / 256), 256>>>();
    // 2: qe = gather(xtf, dst) @ WqT          [R,E,H]   (MODE 1, tf32 A)
    tgemm<0, 1, true><<<dim3(2, GM_E, R), 256>>>(0, TWQ, bq, OFF_QE, E, H, H,
        0, 256L * 256, H, (long)E * H, ei + E, (long)2 * E);
    // 3: k = [xtf[src]|etf] @ WkT             [R,E,H]   (MODE 2, tf32 A)
    tgemm<0, 2, true><<<dim3(2, GM_E, R), 256>>>(0, TWK, bk, OFF_K, E, H, KVDIM,
        0, 272L * 256, H, (long)E * H, ei, (long)2 * E);
    // 4: v = [xtf[src]|etf] @ WvT             [R,E,H]   (MODE 2)
    tgemm<0, 2, true><<<dim3(2, GM_E, R), 256>>>(0, TWV, bv, OFF_V, E, H, KVDIM,
        0, 272L * 256, H, (long)E * H, ei, (long)2 * E);
    // 5: ex = exp(score), denom scatter
    scores_kernel<<<R * E * NH / 256, 256>>>(ei, prior);
    // 6: agg[dst] += w*v
    scatter_kernel<<<R * E * NH * 4 / 256, 256>>>(ei);
    // 7: rel_out = gelu(agg @ WmT + bm)       [R,N,H]   (MODE 0, ldsm+cvt A)
    tgemm<1, 0, false><<<dim3(2, GM_N, R), 256>>>(OFF_AGG, TWM, bm, OFF_REL,
        NNODES, H, H, (long)NNODES * H, 256L * 256, H, (long)NNODES * H, nullptr, 0);
    // 8: h1 = gelu(all_rel @ Wir1T + b_ir1)   [N,H]     (MODE 3, ldsm+cvt A)
    tgemm<1, 3, false><<<dim3(2, GM_N, 1), 256>>>(OFF_REL, TWIR1, b_ir1, OFF_H1,
        NNODES, H, R * H, (long)NNODES * H, 0, 0, 0, nullptr, 0);
    // 9: inter_w = softmax(h1 @ W_ir2 + b_ir2)
    irw_kernel<<<(NNODES * 32 + 255) / 256, 256>>>(W_ir2, b_ir2);
    // 10: inter_agg -> cat[:, :256]; meta-paths
    fuse1_kernel<<<(NNODES * 64 + 255) / 256, 256>>>();
    // 11: stacked = paths @ WmpT + bmp        [3,N,H]   (MODE 0)
    tgemm<0, 0, false><<<dim3(2, GM_N, 3), 256>>>(OFF_PATHS, TWMP, bmp, OFF_STK,
        NNODES, H, H, (long)NNODES * H, 256L * 256, H, (long)NNODES * H, nullptr, 0);
    // 12: tout = tanh(stacked @ Wa1T + ba1)   [3,N,H/2] (MODE 0)
    tgemm<2, 0, false><<<dim3(1, GM_N, 3), 256>>>(OFF_STK, TWA1, ba1, OFF_T,
        NNODES, HHALF, H, (long)NNODES * H, 0, 0, (long)NNODES * HHALF, nullptr, 0);
    // 13: path attention + LN -> cat[:, 256:]
    meta_kernel<<<NNODES, 256>>>(Wa2, g_meta, b_meta);
    // 14: combined = gelu(cat @ WcT + bc)     [N,H]     (MODE 0)
    tgemm<1, 0, false><<<dim3(2, GM_N, 1), 256>>>(OFF_CAT, TWC, bc, OFF_COMB,
        NNODES, H, 2 * H, 0, 0, 0, 0, nullptr, 0);
    // 15: out = LN(x + combined)
    final_kernel<<<NNODES, 256>>>(x, g_out, b_out, out);
}

// round 15
// speedup vs baseline: 1.5550x; 1.5550x over previous
#include <cuda_runtime.h>
#include <cstdint>

// Problem constants
#define NNODES 50000
#define R      6
#define E      32768
#define H      256
#define F      16
#define NH     8
#define HD     32
#define KVDIM  272      // H + F
#define HHALF  128      // H/2

// ---------------- scratch arena (lifetime-aliased) ----------------
constexpr long KV_F = (long)R * E * KVDIM;
constexpr long QE_F = (long)R * E * H;

constexpr long OFF_KV  = 0;
constexpr long OFF_QE  = OFF_KV + KV_F;
constexpr long OFF_K   = OFF_QE + QE_F;
constexpr long OFF_V   = OFF_K + QE_F;
constexpr long ENDA    = OFF_V + QE_F;

// tf32 copies of x/eattr live in the dead KV region (dead before PATHS is written)
constexpr long OFF_XTF = 0;                                 // N*H
constexpr long OFF_ETF = OFF_XTF + (long)NNODES * H;        // R*E*F
static_assert(OFF_ETF + (long)R * E * F <= KV_F, "xtf/etf overflow");

// aliases into [0, ENDA): qe/k/v (and xtf/etf) dead by the time these are written
constexpr long OFF_PATHS = 0;
constexpr long OFF_STK   = OFF_PATHS + (long)3 * NNODES * H;
constexpr long OFF_T     = OFF_STK + (long)3 * NNODES * H;
constexpr long OFF_CAT   = OFF_T + (long)3 * NNODES * HHALF;
constexpr long OFF_COMB  = OFF_CAT + (long)NNODES * 2 * H;
static_assert(OFF_COMB + (long)NNODES * H <= ENDA, "alias overflow");

constexpr long OFF_AGG    = ENDA;
constexpr long OFF_REL    = OFF_AGG + (long)R * NNODES * H;
constexpr long OFF_EX     = OFF_REL + (long)R * NNODES * H;
constexpr long OFF_DEN    = OFF_EX + (long)R * E * NH;
constexpr long OFF_H1     = OFF_DEN + (long)R * NNODES * NH;
constexpr long OFF_IW     = OFF_H1 + (long)NNODES * H;

// transposed+tf32 weights tail  (dst[b][n][k] = cvt(src[b][k][n]))
constexpr long OFF_WT  = OFF_IW + (long)NNODES * R;
constexpr long TWQ   = OFF_WT;                  // 6*256*256
constexpr long TWK   = TWQ  + 6L * 256 * 256;   // 6*272*256  (as [256 n][272 k])
constexpr long TWV   = TWK  + 6L * 272 * 256;
constexpr long TWM   = TWV  + 6L * 272 * 256;   // 6*256*256
constexpr long TWIR1 = TWM  + 6L * 256 * 256;   // [256 n][1536 k]
constexpr long TWMP  = TWIR1 + 1536L * 256;     // 3*256*256
constexpr long TWA1  = TWMP + 3L * 256 * 256;   // [128 n][256 k]
constexpr long TWC   = TWA1 + 256L * 128;       // [256 n][512 k]
constexpr long ARENA_F = TWC + 512L * 256;

__device__ __align__(16) float g_arena[ARENA_F];

// ---------------- helpers ----------------
template<int EPI>
__device__ __forceinline__ float act(float v) {
    if (EPI == 1) return 0.5f * v * (1.f + erff(v * 0.70710678118654752f)); // exact gelu
    if (EPI == 2) return tanhf(v);
    return v;
}

__device__ __forceinline__ uint32_t f2tf32(float f) {
    uint32_t u;
    asm("cvt.rna.tf32.f32 %0, %1;" : "=r"(u) : "f"(f));
    return u;
}

__device__ __forceinline__ void mma8(float* d, const uint32_t* a, const uint32_t* b) {
    asm volatile("mma.sync.aligned.m16n8k8.row.col.f32.tf32.tf32.f32 "
        "{%0,%1,%2,%3}, {%4,%5,%6,%7}, {%8,%9}, {%0,%1,%2,%3};"
        : "+f"(d[0]), "+f"(d[1]), "+f"(d[2]), "+f"(d[3])
        : "r"(a[0]), "r"(a[1]), "r"(a[2]), "r"(a[3]), "r"(b[0]), "r"(b[1]));
}

#define LDSM4(r0, r1, r2, r3, addr) \
    asm volatile("ldmatrix.sync.aligned.m8n8.x4.shared.b16 {%0,%1,%2,%3}, [%4];" \
        : "=r"(r0), "=r"(r1), "=r"(r2), "=r"(r3) : "r"(addr))

__device__ __forceinline__ uint32_t smem_u32(const void* p) {
    return (uint32_t)__cvta_generic_to_shared(p);
}

__device__ __forceinline__ void cp16(uint32_t dst, const void* src, int sz) {
    asm volatile("cp.async.cg.shared.global [%0], [%1], 16, %2;"
                 :: "r"(dst), "l"(src), "r"(sz));
}

__device__ __forceinline__ float blockReduceSum256(float v, float* red) {
    #pragma unroll
    for (int o = 16; o; o >>= 1) v += __shfl_xor_sync(0xffffffffu, v, o);
    int lane = threadIdx.x & 31, w = threadIdx.x >> 5;
    if (lane == 0) red[w] = v;
    __syncthreads();
    float s = (threadIdx.x < 8) ? red[threadIdx.x] : 0.f;
    if (w == 0) {
        #pragma unroll
        for (int o = 4; o; o >>= 1) s += __shfl_xor_sync(0xffffffffu, s, o);
        if (lane == 0) red[0] = s;
    }
    __syncthreads();
    s = red[0];
    __syncthreads();
    return s;
}

// ---------------- prepass: tf32 rounding / weight transpose ----------------
__global__ void cvt_kernel(const float* __restrict__ src, long dstOff, long n) {
    long i = (long)blockIdx.x * 256 + threadIdx.x;
    if (i < n) g_arena[dstOff + i] = __uint_as_float(f2tf32(src[i]));
}

// dst linear: b*N*K + n*K + k  =  cvt(src[b*K*N + k*N + n])
__global__ void trans_kernel(const float* __restrict__ src, long dstOff, int K, int N, int nb) {
    long i = (long)blockIdx.x * 256 + threadIdx.x;
    long tot = (long)K * N * nb;
    if (i >= tot) return;
    int k = (int)(i % K);
    long t2 = i / K;
    int n = (int)(t2 % N);
    int b = (int)(t2 / N);
    g_arena[dstOff + i] = __uint_as_float(f2tf32(src[((long)b * K + k) * N + n]));
}

// ---------------- batched TF32 GEMM: 3-stage cp.async + ldmatrix + XOR swizzle
// Stage layout (A and B identical): [128 rows][16 floats], XOR chunk-swizzle:
//   logical 4-float chunk c of row r stored at chunk c ^ ((r>>1)&3).
// 3 stages x (8KB A + 8KB B) = 49,152 B static (== 48KB cap).
// All operands loaded via ldmatrix.x4.b16 (4 tf32 = one 16B "b16 row").
// ATF32=true: A source already tf32 (no cvt); false: cvt.rna the LDSM regs.
// A source by MODE: 0 arena linear | 1 xtf gather | 2 xtf/etf concat | 3 R-concat
// __launch_bounds__(256, 2): force <=128 regs so 2 CTAs/SM always fit (the
// R12 regression was this exact cliff).
#define NSTAGE 3
constexpr int STG_F = 128 * 16;            // 2048 floats per stage
constexpr uint32_t STG_B = STG_F * 4;      // 8192 bytes

template<int EPI, int MODE, bool ATF32>
__global__ __launch_bounds__(256, 2)
void tgemm(long aOff, long bOff, const float* __restrict__ bias,
           long cOff, int M, int Nc, int K,
           long sA, long sB, long sBias, long sC,
           const int* __restrict__ aidx, long sIdx)
{
    __shared__ __align__(16) float Asm[NSTAGE * STG_F];
    __shared__ __align__(16) float Bsm[NSTAGE * STG_F];

    int bz = blockIdx.z;
    const float* biasp = bias + bz * sBias;
    float* C = g_arena + cOff + bz * sC;

    int t = threadIdx.x;
    int m0 = blockIdx.y * 128, n0 = blockIdx.x * 128;

    int arow = t >> 1, acolg = (t & 1) * 8;    // per-thread: row, 8-float col group

    int gr = m0 + arow;
    bool avalid = gr < M;
    int asz = avalid ? 16 : 0;                 // 0 => cp.async zero-fill
    int grc = avalid ? gr : 0;

    // A source base
    const float* abase = nullptr;
    const float* a2base = nullptr;
    if (MODE == 0) abase = g_arena + aOff + bz * sA + (long)grc * K + acolg;
    if (MODE == 1) abase = g_arena + OFF_XTF + (long)aidx[bz * sIdx + grc] * 256 + acolg;
    if (MODE == 2) {
        abase  = g_arena + OFF_XTF + (long)aidx[bz * sIdx + grc] * 256;
        a2base = g_arena + OFF_ETF + ((long)bz * E + grc) * 16;
    }
    if (MODE == 3) a2base = g_arena + aOff + (long)grc * 256;

    // B source: transposed weights [Nc][K]
    const float* bbase = g_arena + bOff + bz * sB + (long)(n0 + arow) * K + acolg;

    // swizzled cp.async destinations (chunk = 4 floats = 16B)
    int wsw = (arow >> 1) & 3;                       // write swizzle for this row
    int c0 = (acolg >> 2), c1 = c0 + 1;              // logical chunks {0,1} or {2,3}
    uint32_t rowB = (uint32_t)(arow * 64);           // row byte offset
    uint32_t aD1 = smem_u32(Asm) + rowB + (uint32_t)((c0 ^ wsw) << 4);
    uint32_t aD2 = smem_u32(Asm) + rowB + (uint32_t)((c1 ^ wsw) << 4);
    uint32_t bD1 = smem_u32(Bsm) + rowB + (uint32_t)((c0 ^ wsw) << 4);
    uint32_t bD2 = smem_u32(Bsm) + rowB + (uint32_t)((c1 ^ wsw) << 4);

    int lane = t & 31, w = t >> 5;
    int gid = lane >> 2, tig = lane & 3;
    int wm0 = (w & 1) * 64, wn0 = (w >> 1) * 32;

    // ldmatrix per-thread row/chunk (b16 m8n8 trick: 1 matrix row = 4 tf32)
    uint32_t aRow = (uint32_t)((lane & 7) + ((lane >> 3) & 1) * 8);
    uint32_t aChk = (uint32_t)(lane >> 4);           // 0/1
    uint32_t aRB[4]; int aSW[4];
    #pragma unroll
    for (int mf = 0; mf < 4; mf++) {
        uint32_t row = (uint32_t)(wm0 + mf * 16) + aRow;
        aRB[mf] = smem_u32(Asm) + row * 64;
        aSW[mf] = (int)((row >> 1) & 3);
    }
    uint32_t bRow = (uint32_t)((lane & 7) + (lane >> 4) * 8);
    uint32_t bChk = (uint32_t)((lane >> 3) & 1);     // 0/1
    uint32_t bRB[2]; int bSW[2];
    #pragma unroll
    for (int p = 0; p < 2; p++) {
        uint32_t row = (uint32_t)(wn0 + p * 16) + bRow;
        bRB[p] = smem_u32(Bsm) + row * 64;
        bSW[p] = (int)((row >> 1) & 3);
    }

    float d[4][4][4];
    #pragma unroll
    for (int mf = 0; mf < 4; mf++)
        #pragma unroll
        for (int nf = 0; nf < 4; nf++)
            #pragma unroll
            for (int i = 0; i < 4; i++) d[mf][nf][i] = 0.f;

    int T = K >> 4;

    auto issue = [&](int kt, int s) {
        const float* ap;
        if (MODE == 0 || MODE == 1) {
            ap = abase + (long)kt * 16;
        } else if (MODE == 2) {
            int kcol = kt * 16 + acolg;
            ap = (kcol < 256) ? (abase + kcol) : (a2base + (kcol - 256));
        } else { // MODE 3
            int kcol = kt * 16 + acolg;
            int b = kcol >> 8;
            ap = a2base + (long)b * sA + (kcol & 255);
        }
        uint32_t so = (uint32_t)s * STG_B;
        cp16(aD1 + so, ap, asz);
        cp16(aD2 + so, ap + 4, asz);
        const float* bp = bbase + (long)kt * 16;
        cp16(bD1 + so, bp, 16);
        cp16(bD2 + so, bp + 4, 16);
    };

    // prologue: fill 2 stages
    #pragma unroll
    for (int p = 0; p < NSTAGE - 1; p++) {
        if (p < T) issue(p, p);
        asm volatile("cp.async.commit_group;");
    }

    int s = 0;
    for (int kt = 0; kt < T; kt++) {
        asm volatile("cp.async.wait_group 1;" ::: "memory");
        __syncthreads();                       // all warps past prev reads of recycled stage
        int ktn = kt + NSTAGE - 1;
        int sn = s + NSTAGE - 1; if (sn >= NSTAGE) sn -= NSTAGE;
        if (ktn < T) issue(ktn, sn);
        asm volatile("cp.async.commit_group;");

        uint32_t sOff = (uint32_t)s * STG_B;
        #pragma unroll
        for (int ks = 0; ks < 16; ks += 8) {
            int clA = (int)aChk + ((ks >> 3) << 1);   // logical chunk for A ldsm
            int clB = (int)bChk + ((ks >> 3) << 1);
            uint32_t af[4][4], bf[4][2];
            #pragma unroll
            for (int mf = 0; mf < 4; mf++) {
                LDSM4(af[mf][0], af[mf][1], af[mf][2], af[mf][3],
                      aRB[mf] + sOff + (uint32_t)(((clA ^ aSW[mf])) << 4));
                if (!ATF32) {
                    #pragma unroll
                    for (int i = 0; i < 4; i++)
                        af[mf][i] = f2tf32(__uint_as_float(af[mf][i]));
                }
            }
            LDSM4(bf[0][0], bf[0][1], bf[1][0], bf[1][1],
                  bRB[0] + sOff + (uint32_t)(((clB ^ bSW[0])) << 4));
            LDSM4(bf[2][0], bf[2][1], bf[3][0], bf[3][1],
                  bRB[1] + sOff + (uint32_t)(((clB ^ bSW[1])) << 4));
            #pragma unroll
            for (int mf = 0; mf < 4; mf++)
                #pragma unroll
                for (int nf = 0; nf < 4; nf++)
                    mma8(d[mf][nf], af[mf], bf[nf]);
        }
        if (++s == NSTAGE) s = 0;
    }

    // epilogue
    #pragma unroll
    for (int mf = 0; mf < 4; mf++) {
        int r0 = m0 + wm0 + mf * 16 + gid;
        int r1 = r0 + 8;
        #pragma unroll
        for (int nf = 0; nf < 4; nf++) {
            int c0e = n0 + wn0 + nf * 8 + tig * 2;
            float bb0 = biasp[c0e], bb1 = biasp[c0e + 1];
            if (r0 < M) {
                float* cp = C + (long)r0 * Nc + c0e;
                cp[0] = act<EPI>(d[mf][nf][0] + bb0);
                cp[1] = act<EPI>(d[mf][nf][1] + bb1);
            }
            if (r1 < M) {
                float* cp = C + (long)r1 * Nc + c0e;
                cp[0] = act<EPI>(d[mf][nf][2] + bb0);
                cp[1] = act<EPI>(d[mf][nf][3] + bb1);
            }
        }
    }
}

// ---------------- elementwise / scatter kernels ----------------
__global__ void zero_kernel() {
    long i = (long)blockIdx.x * 256 + threadIdx.x;
    float4 z = make_float4(0.f, 0.f, 0.f, 0.f);
    if (i < (long)R * NNODES * H / 4)  ((float4*)(g_arena + OFF_AGG))[i] = z;
    if (i < (long)R * NNODES * NH / 4) ((float4*)(g_arena + OFF_DEN))[i] = z;
}

// ex = exp(score); denom[dst] += ex   (no max-sub: scores are bounded ~|4|)
__global__ void scores_kernel(const int* __restrict__ ei, const float* __restrict__ prior) {
    int t = blockIdx.x * 256 + threadIdx.x;
    if (t >= R * E * NH) return;
    int nh = t & 7;
    int e  = (t >> 3) & (E - 1);
    int r  = t >> 18;
    long base = ((long)r * E + e) * H + nh * HD;
    const float4* q4 = (const float4*)(g_arena + OFF_QE + base);
    const float4* k4 = (const float4*)(g_arena + OFF_K + base);
    float s = 0.f;
    #pragma unroll
    for (int i = 0; i < 8; i++) {
        float4 a = q4[i], b = k4[i];
        s += a.x*b.x + a.y*b.y + a.z*b.z + a.w*b.w;
    }
    s *= 0.17677669529663687f;      // 1/sqrt(32)
    s *= prior[r * NH + nh];
    float ex = expf(s);
    g_arena[OFF_EX + ((long)r * E + e) * NH + nh] = ex;
    int dst = ei[((long)r * 2 + 1) * E + e];
    atomicAdd(&g_arena[OFF_DEN + ((long)r * NNODES + dst) * NH + nh], ex);
}

// agg[dst] += w * v  (8 dims per thread, vectorized f32 reductions)
__global__ void scatter_kernel(const int* __restrict__ ei) {
    int t = blockIdx.x * 256 + threadIdx.x;
    if (t >= R * E * NH * 4) return;
    int c  = t & 3;
    int nh = (t >> 2) & 7;
    int e  = (t >> 5) & (E - 1);
    int r  = t >> 20;
    int dst = ei[((long)r * 2 + 1) * E + e];
    float ex = g_arena[OFF_EX + ((long)r * E + e) * NH + nh];
    float dn = g_arena[OFF_DEN + ((long)r * NNODES + dst) * NH + nh];
    float w = ex / (dn + 1e-16f);
    long vb = ((long)r * E + e) * H + nh * HD + c * 8;
    float4 v0 = *(const float4*)(g_arena + OFF_V + vb);
    float4 v1 = *(const float4*)(g_arena + OFF_V + vb + 4);
    float* ag = g_arena + OFF_AGG + ((long)r * NNODES + dst) * H + nh * HD + c * 8;
    asm volatile("red.global.add.v4.f32 [%0], {%1,%2,%3,%4};"
                 :: "l"(ag), "f"(w*v0.x), "f"(w*v0.y), "f"(w*v0.z), "f"(w*v0.w) : "memory");
    asm volatile("red.global.add.v4.f32 [%0], {%1,%2,%3,%4};"
                 :: "l"(ag+4), "f"(w*v1.x), "f"(w*v1.y), "f"(w*v1.z), "f"(w*v1.w) : "memory");
}

// inter_w[n,:] = softmax(h1[n,:] @ W_ir2 + b_ir2)   (one warp per node)
__global__ void irw_kernel(const float* __restrict__ W_ir2, const float* __restrict__ b_ir2) {
    int gt = blockIdx.x * 256 + threadIdx.x;
    int warp = gt >> 5, lane = gt & 31;
    if (warp >= NNODES) return;
    const float* hr = g_arena + OFF_H1 + (long)warp * H;
    float acc[R];
    #pragma unroll
    for (int r = 0; r < R; r++) acc[r] = 0.f;
    for (int k = lane; k < H; k += 32) {
        float hv = hr[k];
        #pragma unroll
        for (int r = 0; r < R; r++) acc[r] += hv * W_ir2[k * R + r];
    }
    #pragma unroll
    for (int r = 0; r < R; r++)
        #pragma unroll
        for (int o = 16; o; o >>= 1) acc[r] += __shfl_xor_sync(0xffffffffu, acc[r], o);
    if (lane == 0) {
        float l[R], mx = -1e30f;
        #pragma unroll
        for (int r = 0; r < R; r++) { l[r] = acc[r] + b_ir2[r]; mx = fmaxf(mx, l[r]); }
        float s = 0.f;
        #pragma unroll
        for (int r = 0; r < R; r++) { l[r] = expf(l[r] - mx); s += l[r]; }
        #pragma unroll
        for (int r = 0; r < R; r++) g_arena[OFF_IW + (long)warp * R + r] = l[r] / s;
    }
}

// inter_agg -> cat[:, 0:256]; meta-paths -> paths[3,N,H]
__global__ void fuse1_kernel() {
    int t = blockIdx.x * 256 + threadIdx.x;
    if (t >= NNODES * 64) return;
    int h4 = t & 63;
    long n = t >> 6;
    float w[R];
    #pragma unroll
    for (int r = 0; r < R; r++) w[r] = g_arena[OFF_IW + n * R + r];
    float4 rv[R];
    #pragma unroll
    for (int r = 0; r < R; r++)
        rv[r] = ((const float4*)(g_arena + OFF_REL))[((long)r * NNODES + n) * 64 + h4];
    float4 ia;
    ia.x = ia.y = ia.z = ia.w = 0.f;
    #pragma unroll
    for (int r = 0; r < R; r++) {
        ia.x += w[r] * rv[r].x; ia.y += w[r] * rv[r].y;
        ia.z += w[r] * rv[r].z; ia.w += w[r] * rv[r].w;
    }
    ((float4*)(g_arena + OFF_CAT))[n * 128 + h4] = ia;
    float4 p0, p1, p2;
    p0.x = rv[2].x + rv[3].x; p0.y = rv[2].y + rv[3].y; p0.z = rv[2].z + rv[3].z; p0.w = rv[2].w + rv[3].w;
    p1.x = rv[4].x + rv[0].x; p1.y = rv[4].y + rv[0].y; p1.z = rv[4].z + rv[0].z; p1.w = rv[4].w + rv[0].w;
    p2.x = rv[1].x + rv[5].x; p2.y = rv[1].y + rv[5].y; p2.z = rv[1].z + rv[5].z; p2.w = rv[1].w + rv[5].w;
    float4* pp = (float4*)(g_arena + OFF_PATHS);
    pp[((long)0 * NNODES + n) * 64 + h4] = p0;
    pp[((long)1 * NNODES + n) * 64 + h4] = p1;
    pp[((long)2 * NNODES + n) * 64 + h4] = p2;
}

// path-attention + weighted sum + LN -> cat[:, 256:512]   (block per node)
__global__ void meta_kernel(const float* __restrict__ Wa2,
                            const float* __restrict__ g_meta, const float* __restrict__ b_meta) {
    __shared__ float red[8];
    __shared__ float sw[3];
    long n = blockIdx.x;
    int t = threadIdx.x;
    float p0 = 0.f, p1 = 0.f, p2 = 0.f;
    if (t < HHALF) {
        float w2 = Wa2[t];
        const float* tb = g_arena + OFF_T;
        p0 = tb[((long)0 * NNODES + n) * HHALF + t] * w2;
        p1 = tb[((long)1 * NNODES + n) * HHALF + t] * w2;
        p2 = tb[((long)2 * NNODES + n) * HHALF + t] * w2;
    }
    float l0 = blockReduceSum256(p0, red);
    float l1 = blockReduceSum256(p1, red);
    float l2 = blockReduceSum256(p2, red);
    if (t == 0) {
        float mx = fmaxf(l0, fmaxf(l1, l2));
        float e0 = expf(l0 - mx), e1 = expf(l1 - mx), e2 = expf(l2 - mx);
        float s = e0 + e1 + e2;
        sw[0] = e0 / s; sw[1] = e1 / s; sw[2] = e2 / s;
    }
    __syncthreads();
    const float* sb = g_arena + OFF_STK;
    float mp = sw[0] * sb[((long)0 * NNODES + n) * H + t]
             + sw[1] * sb[((long)1 * NNODES + n) * H + t]
             + sw[2] * sb[((long)2 * NNODES + n) * H + t];
    float s1 = blockReduceSum256(mp, red);
    float s2 = blockReduceSum256(mp * mp, red);
    float mu = s1 * (1.f / H);
    float var = s2 * (1.f / H) - mu * mu;
    g_arena[OFF_CAT + n * 512 + 256 + t] =
        (mp - mu) * rsqrtf(var + 1e-5f) * g_meta[t] + b_meta[t];
}

// out = LN(x + combined)
__global__ void final_kernel(const float* __restrict__ x,
                             const float* __restrict__ g, const float* __restrict__ b,
                             float* __restrict__ out) {
    __shared__ float red[8];
    long n = blockIdx.x;
    int t = threadIdx.x;
    float v = x[n * H + t] + g_arena[OFF_COMB + n * H + t];
    float s1 = blockReduceSum256(v, red);
    float s2 = blockReduceSum256(v * v, red);
    float mu = s1 * (1.f / H);
    float var = s2 * (1.f / H) - mu * mu;
    out[n * H + t] = (v - mu) * rsqrtf(var + 1e-5f) * g[t] + b[t];
}

// ---------------- launcher ----------------
extern "C" void kernel_launch(void* const* d_in, const int* in_sizes, int n_in,
                              void* d_out, int out_size) {
    const float* x      = (const float*)d_in[0];
    const int*   ei     = (const int*)  d_in[1];
    const float* eattr  = (const float*)d_in[2];
    const float* Wq     = (const float*)d_in[3];
    const float* bq     = (const float*)d_in[4];
    const float* Wk     = (const float*)d_in[5];
    const float* bk     = (const float*)d_in[6];
    const float* Wv     = (const float*)d_in[7];
    const float* bv     = (const float*)d_in[8];
    const float* prior  = (const float*)d_in[9];
    const float* Wm     = (const float*)d_in[10];
    const float* bm     = (const float*)d_in[11];
    const float* W_ir1  = (const float*)d_in[12];
    const float* b_ir1  = (const float*)d_in[13];
    const float* W_ir2  = (const float*)d_in[14];
    const float* b_ir2  = (const float*)d_in[15];
    const float* Wmp    = (const float*)d_in[16];
    const float* bmp    = (const float*)d_in[17];
    const float* Wa1    = (const float*)d_in[18];
    const float* ba1    = (const float*)d_in[19];
    const float* Wa2    = (const float*)d_in[20];
    const float* g_meta = (const float*)d_in[21];
    const float* b_meta = (const float*)d_in[22];
    const float* Wc     = (const float*)d_in[23];
    const float* bc     = (const float*)d_in[24];
    const float* g_out  = (const float*)d_in[25];
    const float* b_out  = (const float*)d_in[26];
    float* out = (float*)d_out;

    const int GM_N = (NNODES + 127) / 128;   // 391
    const int GM_E = E / 128;                // 256

    // 0: prepass — tf32 copies of x/eattr, transposed tf32 weights
    cvt_kernel<<<(int)(((long)NNODES * H + 255) / 256), 256>>>(x, OFF_XTF, (long)NNODES * H);
    cvt_kernel<<<(int)(((long)R * E * F + 255) / 256), 256>>>(eattr, OFF_ETF, (long)R * E * F);
    trans_kernel<<<(6 * 256 * 256 + 255) / 256, 256>>>(Wq, TWQ, 256, 256, 6);
    trans_kernel<<<(6 * 272 * 256 + 255) / 256, 256>>>(Wk, TWK, 272, 256, 6);
    trans_kernel<<<(6 * 272 * 256 + 255) / 256, 256>>>(Wv, TWV, 272, 256, 6);
    trans_kernel<<<(6 * 256 * 256 + 255) / 256, 256>>>(Wm, TWM, 256, 256, 6);
    trans_kernel<<<(1536 * 256 + 255) / 256, 256>>>(W_ir1, TWIR1, 1536, 256, 1);
    trans_kernel<<<(3 * 256 * 256 + 255) / 256, 256>>>(Wmp, TWMP, 256, 256, 3);
    trans_kernel<<<(256 * 128 + 255) / 256, 256>>>(Wa1, TWA1, 256, 128, 1);
    trans_kernel<<<(512 * 256 + 255) / 256, 256>>>(Wc, TWC, 512, 256, 1);
    // 1: zero accumulators (agg, denom) — float4 stores
    zero_kernel<<<(int)((((long)R * NNODES * H / 4) + 255) / 256), 256>>>();
    // 2: qe = gather(xtf, dst) @ WqT          [R,E,H]   (MODE 1, tf32 A)
    tgemm<0, 1, true><<<dim3(2, GM_E, R), 256>>>(0, TWQ, bq, OFF_QE, E, H, H,
        0, 256L * 256, H, (long)E * H, ei + E, (long)2 * E);
    // 3: k = [xtf[src]|etf] @ WkT             [R,E,H]   (MODE 2, tf32 A)
    tgemm<0, 2, true><<<dim3(2, GM_E, R), 256>>>(0, TWK, bk, OFF_K, E, H, KVDIM,
        0, 272L * 256, H, (long)E * H, ei, (long)2 * E);
    // 4: v = [xtf[src]|etf] @ WvT             [R,E,H]   (MODE 2)
    tgemm<0, 2, true><<<dim3(2, GM_E, R), 256>>>(0, TWV, bv, OFF_V, E, H, KVDIM,
        0, 272L * 256, H, (long)E * H, ei, (long)2 * E);
    // 5: ex = exp(score), denom scatter
    scores_kernel<<<R * E * NH / 256, 256>>>(ei, prior);
    // 6: agg[dst] += w*v
    scatter_kernel<<<R * E * NH * 4 / 256, 256>>>(ei);
    // 7: rel_out = gelu(agg @ WmT + bm)       [R,N,H]   (MODE 0, ldsm+cvt A)
    tgemm<1, 0, false><<<dim3(2, GM_N, R), 256>>>(OFF_AGG, TWM, bm, OFF_REL,
        NNODES, H, H, (long)NNODES * H, 256L * 256, H, (long)NNODES * H, nullptr, 0);
    // 8: h1 = gelu(all_rel @ Wir1T + b_ir1)   [N,H]     (MODE 3, ldsm+cvt A)
    tgemm<1, 3, false><<<dim3(2, GM_N, 1), 256>>>(OFF_REL, TWIR1, b_ir1, OFF_H1,
        NNODES, H, R * H, (long)NNODES * H, 0, 0, 0, nullptr, 0);
    // 9: inter_w = softmax(h1 @ W_ir2 + b_ir2)
    irw_kernel<<<(NNODES * 32 + 255) / 256, 256>>>(W_ir2, b_ir2);
    // 10: inter_agg -> cat[:, :256]; meta-paths
    fuse1_kernel<<<(NNODES * 64 + 255) / 256, 256>>>();
    // 11: stacked = paths @ WmpT + bmp        [3,N,H]   (MODE 0)
    tgemm<0, 0, false><<<dim3(2, GM_N, 3), 256>>>(OFF_PATHS, TWMP, bmp, OFF_STK,
        NNODES, H, H, (long)NNODES * H, 256L * 256, H, (long)NNODES * H, nullptr, 0);
    // 12: tout = tanh(stacked @ Wa1T + ba1)   [3,N,H/2] (MODE 0)
    tgemm<2, 0, false><<<dim3(1, GM_N, 3), 256>>>(OFF_STK, TWA1, ba1, OFF_T,
        NNODES, HHALF, H, (long)NNODES * H, 0, 0, (long)NNODES * HHALF, nullptr, 0);
    // 13: path attention + LN -> cat[:, 256:]
    meta_kernel<<<NNODES, 256>>>(Wa2, g_meta, b_meta);
    // 14: combined = gelu(cat @ WcT + bc)     [N,H]     (MODE 0)
    tgemm<1, 0, false><<<dim3(2, GM_N, 1), 256>>>(OFF_CAT, TWC, bc, OFF_COMB,
        NNODES, H, 2 * H, 0, 0, 0, 0, nullptr, 0);
    // 15: out = LN(x + combined)
    final_kernel<<<NNODES, 256>>>(x, g_out, b_out, out);
}